// round 13
// baseline (speedup 1.0000x reference)
#include <cuda_runtime.h>
#include <cuda_bf16.h>
#include <cstdint>
#include <math.h>

#define Tn    2048
#define HIDn  2048
#define Hn    32
#define HKVn  2
#define Dn    64
#define Gn    2
#define HGn   16
#define BLKn  32
#define NSELn 8
#define WINn  256
#define NBn   64
#define OUTDn 2400
#define NPADn 2432          /* 19*128 */
#define K2n   6144          /* 3x K=2048 : [ah,ah,al] x [bh,bl,bh] */
#define KOFF  (Hn*Dn)
#define VOFF  (KOFF + HKVn*Dn)
#define WOFF  (VOFF + HKVn*Dn)
#define NEGf  (-1e30f)
#define SCALEf 0.125f

// ---------------- scratch ----------------
__device__ float g_qkvw[Tn*OUTDn];
__device__ float g_q[Tn*Hn*Dn];
__device__ float g_k[Tn*HKVn*Dn];
__device__ float g_kcmp[NBn*Gn*Dn];
__device__ float g_vcmp[NBn*Gn*Dn];
__device__ float g_pcmp[Tn*Hn*NBn];
__device__ float g_ocmp[Tn*Hn*Dn];
__device__ float g_osel[Tn*Hn*Dn];
__device__ float g_owin[Tn*Hn*Dn];
__device__ int   g_selidx[Tn*Gn*NSELn];
__device__ __align__(16) __nv_bfloat16 g_a2x[(size_t)Tn*K2n];
__device__ __align__(16) __nv_bfloat16 g_a2o[(size_t)Tn*K2n];
__device__ __align__(16) __nv_bfloat16 g_b2q[(size_t)NPADn*K2n];
__device__ __align__(16) __nv_bfloat16 g_b2o[(size_t)HIDn*K2n];

// ---------------- helpers ----------------
__device__ __forceinline__ uint32_t smem_u32(const void* p) {
    uint32_t a;
    asm("{ .reg .u64 t; cvta.to.shared.u64 t, %1; cvt.u32.u64 %0, t; }" : "=r"(a) : "l"(p));
    return a;
}
#define CP_ASYNC16(dst, src) \
    asm volatile("cp.async.cg.shared.global [%0], [%1], 16;" :: "r"(dst), "l"(src) : "memory")
#define CP_COMMIT() asm volatile("cp.async.commit_group;" ::: "memory")
#define CP_WAIT1()  asm volatile("cp.async.wait_group 1;" ::: "memory")
#define CP_WAIT0()  asm volatile("cp.async.wait_group 0;" ::: "memory")

__device__ __forceinline__ void ldsm4(uint32_t &r0, uint32_t &r1, uint32_t &r2, uint32_t &r3,
                                      uint32_t addr) {
    asm volatile("ldmatrix.sync.aligned.m8n8.x4.shared.b16 {%0,%1,%2,%3}, [%4];"
                 : "=r"(r0), "=r"(r1), "=r"(r2), "=r"(r3) : "r"(addr));
}
__device__ __forceinline__ void mma_bf16(float* c, uint32_t a0, uint32_t a1, uint32_t a2,
                                         uint32_t a3, uint32_t b0, uint32_t b1) {
    asm volatile("mma.sync.aligned.m16n8k16.row.col.f32.bf16.bf16.f32 "
                 "{%0,%1,%2,%3}, {%4,%5,%6,%7}, {%8,%9}, {%0,%1,%2,%3};"
                 : "+f"(c[0]), "+f"(c[1]), "+f"(c[2]), "+f"(c[3])
                 : "r"(a0), "r"(a1), "r"(a2), "r"(a3), "r"(b0), "r"(b1));
}

__device__ __forceinline__ float warpMax(float v) {
    #pragma unroll
    for (int o = 16; o > 0; o >>= 1) v = fmaxf(v, __shfl_xor_sync(0xffffffffu, v, o));
    return v;
}
__device__ __forceinline__ float warpSum(float v) {
    #pragma unroll
    for (int o = 16; o > 0; o >>= 1) v += __shfl_xor_sync(0xffffffffu, v, o);
    return v;
}
__device__ __forceinline__ void f32_hl(float v, unsigned short &h, unsigned short &l) {
    __nv_bfloat16 bh = __float2bfloat16(v);
    float r = v - __bfloat162float(bh);
    __nv_bfloat16 bl = __float2bfloat16(r);
    h = __bfloat16_as_ushort(bh);
    l = __bfloat16_as_ushort(bl);
}

// ---------------- mma.sync split-bf16 GEMM body ----------------
#define SAst 40
#define STAGE_BYTES (128*SAst*2)
#define STAGE_PAIR  (2*STAGE_BYTES)
#define NSTAGE 3
#define GEMM_SMEM (NSTAGE*STAGE_PAIR)
__device__ __forceinline__ void gemm_body(const __nv_bfloat16* __restrict__ A2,
                                          const __nv_bfloat16* __restrict__ B2,
                                          float* __restrict__ C,
                                          int Nvalid, int ldc) {
    extern __shared__ __align__(16) unsigned char smem[];
    const uint32_t sbase = smem_u32(smem);
    const int tid = threadIdx.x;
    const int lane = tid & 31;
    const int warp = tid >> 5;
    const int wm = warp >> 2;
    const int wn = warp & 3;
    const int m0 = blockIdx.y * 128;
    const int n0 = blockIdx.x * 128;

    const int lrow = tid >> 2;
    const int lk   = (tid & 3) * 8;
    const __nv_bfloat16* aG = A2 + (size_t)(m0 + lrow) * K2n + lk;
    const __nv_bfloat16* bG = B2 + (size_t)(n0 + lrow) * K2n + lk;
    const uint32_t wOff = (uint32_t)(lrow * SAst + lk) * 2;

    float acc[2][4][4];
    #pragma unroll
    for (int i = 0; i < 2; i++)
        #pragma unroll
        for (int j = 0; j < 4; j++)
            #pragma unroll
            for (int r = 0; r < 4; r++) acc[i][j][r] = 0.f;

    const int NK = K2n / 32;

    const uint32_t aRow = (uint32_t)(wm * 32 + (lane & 15));
    const uint32_t aColSel = (uint32_t)((lane >> 4) * 8);
    const int ro = lane >> 3;
    const uint32_t bRow = (uint32_t)(wn * 32 + ((ro & 2) ? 8 : 0) + (lane & 7));
    const uint32_t bColSel = (uint32_t)((ro & 1) ? 8 : 0);

    #pragma unroll
    for (int s = 0; s < 2; s++) {
        uint32_t sA = sbase + (uint32_t)s * STAGE_PAIR;
        uint32_t sB = sA + STAGE_BYTES;
        CP_ASYNC16(sA + wOff, aG + (size_t)s * 32);
        CP_ASYNC16(sB + wOff, bG + (size_t)s * 32);
        CP_COMMIT();
    }

    for (int kc = 0; kc < NK; kc++) {
        if (kc + 2 < NK) CP_WAIT1(); else CP_WAIT0();
        __syncthreads();

        if (kc + 2 < NK) {
            uint32_t st = (uint32_t)((kc + 2) % 3) * STAGE_PAIR;
            uint32_t sA = sbase + st;
            uint32_t sB = sA + STAGE_BYTES;
            CP_ASYNC16(sA + wOff, aG + (size_t)(kc + 2) * 32);
            CP_ASYNC16(sB + wOff, bG + (size_t)(kc + 2) * 32);
            CP_COMMIT();
        }

        uint32_t st = (uint32_t)(kc % 3) * STAGE_PAIR;
        uint32_t sA = sbase + st;
        uint32_t sB = sA + STAGE_BYTES;

        #pragma unroll
        for (int s = 0; s < 2; s++) {
            uint32_t af[2][4];
            #pragma unroll
            for (int i = 0; i < 2; i++) {
                uint32_t addr = sA + ((aRow + i * 16) * SAst + s * 16 + aColSel) * 2;
                ldsm4(af[i][0], af[i][1], af[i][2], af[i][3], addr);
            }
            uint32_t bf[4][2];
            #pragma unroll
            for (int j2 = 0; j2 < 2; j2++) {
                uint32_t addr = sB + ((bRow + j2 * 16) * SAst + s * 16 + bColSel) * 2;
                uint32_t r0, r1, r2, r3;
                ldsm4(r0, r1, r2, r3, addr);
                bf[2*j2][0] = r0; bf[2*j2][1] = r1;
                bf[2*j2+1][0] = r2; bf[2*j2+1][1] = r3;
            }
            #pragma unroll
            for (int i = 0; i < 2; i++)
                #pragma unroll
                for (int j = 0; j < 4; j++)
                    mma_bf16(acc[i][j], af[i][0], af[i][1], af[i][2], af[i][3],
                             bf[j][0], bf[j][1]);
        }
    }

    const int rbase = m0 + wm * 32 + (lane >> 2);
    const int cbase = n0 + wn * 32 + (lane & 3) * 2;
    #pragma unroll
    for (int i = 0; i < 2; i++) {
        #pragma unroll
        for (int j = 0; j < 4; j++) {
            int rr = rbase + i * 16;
            int cc = cbase + j * 8;
            if (cc < Nvalid) {
                float* p0 = C + (size_t)rr * ldc + cc;
                p0[0] = acc[i][j][0];
                if (cc + 1 < Nvalid) p0[1] = acc[i][j][1];
                float* p1 = C + (size_t)(rr + 8) * ldc + cc;
                p1[0] = acc[i][j][2];
                if (cc + 1 < Nvalid) p1[1] = acc[i][j][3];
            }
        }
    }
}

__global__ __launch_bounds__(512) void gemm_mma_qkvw() {
    gemm_body(g_a2x, g_b2q, g_qkvw, OUTDn, OUTDn);
}
__global__ __launch_bounds__(512) void gemm_mma_out(float* __restrict__ C) {
    gemm_body(g_a2o, g_b2o, C, HIDn, HIDn);
}

// ---------------- conversions ----------------
__global__ void conv_x_kernel(const float* __restrict__ x) {
    int idx = blockIdx.x * blockDim.x + threadIdx.x;
    if (idx >= Tn * HIDn) return;
    unsigned short h, l;
    f32_hl(x[idx], h, l);
    unsigned short* p = (unsigned short*)g_a2x + (size_t)idx * 3;
    p[0] = h; p[1] = h; p[2] = l;
}
__device__ __forceinline__ void tr_body(const float* __restrict__ W,
                                        __nv_bfloat16* __restrict__ B2,
                                        int Ncols, int Npad) {
    __shared__ float tile[32][33];
    int n = blockIdx.x * 32 + threadIdx.x;
    int k = blockIdx.y * 32 + threadIdx.y;
    tile[threadIdx.y][threadIdx.x] = (n < Ncols) ? W[(size_t)k * Ncols + n] : 0.f;
    __syncthreads();
    int nn = blockIdx.x * 32 + threadIdx.y;
    int kk = blockIdx.y * 32 + threadIdx.x;
    if (nn < Npad) {
        unsigned short h, l;
        f32_hl(tile[threadIdx.x][threadIdx.y], h, l);
        unsigned short* p = (unsigned short*)B2 + (size_t)nn * K2n + (size_t)kk * 3;
        p[0] = h; p[1] = l; p[2] = h;
    }
}
__global__ void tr_q_kernel(const float* __restrict__ W) { tr_body(W, g_b2q, OUTDn, NPADn); }
__global__ void tr_o_kernel(const float* __restrict__ W) { tr_body(W, g_b2o, HIDn, HIDn); }

// ---------------- RoPE ----------------
__global__ void rope_kernel(const float* __restrict__ cosp, const float* __restrict__ sinp) {
    int idx = blockIdx.x * blockDim.x + threadIdx.x;
    const int total = Tn * (Hn + HKVn) * Dn;
    if (idx >= total) return;
    const int d = idx & 63;
    int rest = idx >> 6;
    const int h = rest % (Hn + HKVn);
    const int t = rest / (Hn + HKVn);
    const float c = cosp[t * Dn + d];
    const float s = sinp[t * Dn + d];
    if (h < Hn) {
        const float* row = g_qkvw + (size_t)t * OUTDn + h * Dn;
        float x = row[d];
        float rot = (d < 32) ? -row[d + 32] : row[d - 32];
        g_q[((size_t)t * Hn + h) * Dn + d] = x * c + rot * s;
    } else {
        const int g = h - Hn;
        const float* row = g_qkvw + (size_t)t * OUTDn + KOFF + g * Dn;
        float x = row[d];
        float rot = (d < 32) ? -row[d + 32] : row[d - 32];
        g_k[((size_t)t * HKVn + g) * Dn + d] = x * c + rot * s;
    }
}

// ---------------- mean-pool ----------------
__global__ void pool_kernel() {
    int idx = blockIdx.x * blockDim.x + threadIdx.x;
    if (idx >= NBn * Gn * Dn) return;
    const int d = idx & 63;
    int rest = idx >> 6;
    const int g = rest % Gn;
    const int n = rest / Gn;
    float sk = 0.f, sv = 0.f;
    #pragma unroll 4
    for (int b = 0; b < BLKn; b++) {
        const int t = n * BLKn + b;
        sk += g_k[((size_t)t * HKVn + g) * Dn + d];
        sv += g_qkvw[(size_t)t * OUTDn + VOFF + g * Dn + d];
    }
    g_kcmp[idx] = sk * (1.f / BLKn);
    g_vcmp[idx] = sv * (1.f / BLKn);
}

// ---------------- compressed attention: CTA per (t,g), warp per head ----------------
__global__ __launch_bounds__(512) void cmp2_kernel() {
    const int t = blockIdx.x, g = blockIdx.y;
    const int tid = threadIdx.x, w = tid >> 5, lane = tid & 31;
    __shared__ float kc[NBn][65], vc[NBn][65], qs[HGn][Dn], ps[HGn][NBn];

    for (int i = tid; i < NBn * Dn; i += 512) {
        int n = i >> 6, d = i & 63;
        kc[n][d] = g_kcmp[((size_t)n * Gn + g) * Dn + d];
        vc[n][d] = g_vcmp[((size_t)n * Gn + g) * Dn + d];
    }
    for (int i = tid; i < HGn * Dn; i += 512) {
        int hg = i >> 6, d = i & 63;
        qs[hg][d] = g_q[((size_t)t * Hn + g * HGn + hg) * Dn + d];
    }
    __syncthreads();

    const int nvis = (t + 1) >> 5;
    float sc[2];
    #pragma unroll
    for (int ii = 0; ii < 2; ii++) {
        const int n = lane + ii * 32;
        float s = NEGf;
        if (n < nvis) {
            float acc = 0.f;
            #pragma unroll
            for (int d = 0; d < Dn; d++) acc = fmaf(qs[w][d], kc[n][d], acc);
            s = acc * SCALEf;
        }
        sc[ii] = s;
    }
    float p0 = 0.f, p1 = 0.f;
    if (nvis > 0) {
        float m = warpMax(fmaxf(sc[0], sc[1]));
        float e0 = expf(sc[0] - m), e1 = expf(sc[1] - m);
        float inv = 1.f / warpSum(e0 + e1);
        p0 = e0 * inv; p1 = e1 * inv;
    }
    ps[w][lane] = p0; ps[w][lane + 32] = p1;
    float* pout = g_pcmp + ((size_t)t * Hn + g * HGn + w) * NBn;
    pout[lane] = p0; pout[lane + 32] = p1;
    __syncwarp();

    float a0 = 0.f, a1 = 0.f;
    for (int n = 0; n < nvis; n++) {
        const float p = ps[w][n];
        a0 = fmaf(p, vc[n][lane], a0);
        a1 = fmaf(p, vc[n][lane + 32], a1);
    }
    float* orow = g_ocmp + ((size_t)t * Hn + g * HGn + w) * Dn;
    orow[lane] = a0; orow[lane + 32] = a1;
}

// ---------------- top-8 ----------------
__global__ void topk_kernel() {
    int idx = blockIdx.x * blockDim.x + threadIdx.x;
    if (idx >= Tn * Gn) return;
    const int g = idx % Gn, t = idx / Gn, tb = t >> 5;
    float imp[NBn];
    for (int n = 0; n < NBn; n++) {
        if (n > tb) { imp[n] = NEGf; continue; }
        float s = 0.f;
        #pragma unroll
        for (int hg = 0; hg < HGn; hg++)
            s += g_pcmp[((size_t)t * Hn + g * HGn + hg) * NBn + n];
        if (n == 0)  s += 1e4f;
        if (n == tb) s += 1e4f;
        imp[n] = s;
    }
    int* sel = g_selidx + ((size_t)t * Gn + g) * NSELn;
    for (int i = 0; i < NSELn; i++) {
        int best = 0; float bv = imp[0];
        for (int n = 1; n < NBn; n++)
            if (imp[n] > bv) { bv = imp[n]; best = n; }
        sel[i] = best;
        imp[best] = -2e30f;
    }
}

// ---------------- selection attention v3: single pass, online softmax ----------------
__global__ __launch_bounds__(512) void sel3_kernel() {
    const int t = blockIdx.x, g = blockIdx.y;
    const int tid = threadIdx.x, w = tid >> 5, lane = tid & 31;
    __shared__ float kb[BLKn][65], vb[BLKn][64], qs[HGn][Dn], ps[HGn][32];
    __shared__ int sel[NSELn];

    for (int i = tid; i < HGn * Dn; i += 512) {
        int hg = i >> 6, d = i & 63;
        qs[hg][d] = g_q[((size_t)t * Hn + g * HGn + hg) * Dn + d];
    }
    if (tid < NSELn) sel[tid] = g_selidx[((size_t)t * Gn + g) * NSELn + tid];
    __syncthreads();

    float m = NEGf, l = 0.f, a0 = 0.f, a1 = 0.f;
    for (int i = 0; i < NSELn; i++) {
        const int base = sel[i] * BLKn;
        for (int j = tid; j < BLKn * Dn; j += 512) {
            int b = j >> 6, d = j & 63;
            kb[b][d] = g_k[((size_t)(base + b) * HKVn + g) * Dn + d];
            vb[b][d] = g_qkvw[(size_t)(base + b) * OUTDn + VOFF + g * Dn + d];
        }
        __syncthreads();
        const int pos = base + lane;
        float s = NEGf;
        if (pos <= t) {
            float acc = 0.f;
            #pragma unroll
            for (int d = 0; d < Dn; d++) acc = fmaf(qs[w][d], kb[lane][d], acc);
            s = acc * SCALEf;
        }
        float mnew = fmaxf(m, warpMax(s));
        float corr = expf(m - mnew);           // all-invalid chunk: exp(0)=1 on zero state
        float e = (pos <= t) ? expf(s - mnew) : 0.f;
        ps[w][lane] = e;
        __syncwarp();
        l = l * corr + warpSum(e);
        a0 *= corr; a1 *= corr;
        #pragma unroll 8
        for (int b = 0; b < BLKn; b++) {
            const float p = ps[w][b];
            a0 = fmaf(p, vb[b][lane], a0);
            a1 = fmaf(p, vb[b][lane + 32], a1);
        }
        m = mnew;
        __syncthreads();
    }
    float inv = 1.f / l;
    float* orow = g_osel + ((size_t)t * Hn + g * HGn + w) * Dn;
    orow[lane] = a0 * inv; orow[lane + 32] = a1 * inv;
}

// ---------------- sliding window v4: single pass, online softmax ----------------
__global__ __launch_bounds__(512) void win4_kernel() {
    const int t = blockIdx.x, g = blockIdx.y;
    const int tid = threadIdx.x, w = tid >> 5, lane = tid & 31;
    __shared__ float kb[BLKn][65], vb[BLKn][64], qs[HGn][Dn], ps[HGn][32];

    for (int i = tid; i < HGn * Dn; i += 512) {
        int hg = i >> 6, d = i & 63;
        qs[hg][d] = g_q[((size_t)t * Hn + g * HGn + hg) * Dn + d];
    }
    __syncthreads();

    const int p0 = t - (WINn - 1);
    float m = NEGf, l = 0.f, a0 = 0.f, a1 = 0.f;
    for (int i = 0; i < 8; i++) {
        const int base = p0 + i * 32;
        for (int j = tid; j < BLKn * Dn; j += 512) {
            int b = j >> 6, d = j & 63;
            int row = base + b; if (row < 0) row = 0;
            kb[b][d] = g_k[((size_t)row * HKVn + g) * Dn + d];
            vb[b][d] = g_qkvw[(size_t)row * OUTDn + VOFF + g * Dn + d];
        }
        __syncthreads();
        const int pos = base + lane;
        float s = NEGf;
        if (pos >= 0) {
            float acc = 0.f;
            #pragma unroll
            for (int d = 0; d < Dn; d++) acc = fmaf(qs[w][d], kb[lane][d], acc);
            s = acc * SCALEf;
        }
        float mnew = fmaxf(m, warpMax(s));
        float corr = expf(m - mnew);
        float e = (pos >= 0) ? expf(s - mnew) : 0.f;
        ps[w][lane] = e;
        __syncwarp();
        l = l * corr + warpSum(e);
        a0 *= corr; a1 *= corr;
        #pragma unroll 8
        for (int b = 0; b < BLKn; b++) {
            const float p = ps[w][b];
            a0 = fmaf(p, vb[b][lane], a0);
            a1 = fmaf(p, vb[b][lane + 32], a1);
        }
        m = mnew;
        __syncthreads();
    }
    float inv = 1.f / l;
    float* orow = g_owin + ((size_t)t * Hn + g * HGn + w) * Dn;
    orow[lane] = a0 * inv; orow[lane + 32] = a1 * inv;
}

// ---------------- gated combine -> 3-term split A operand ----------------
__global__ void combine_kernel() {
    int idx = blockIdx.x * blockDim.x + threadIdx.x;
    if (idx >= Tn * Hn * Dn) return;
    const int d = idx & 63;
    int rest = idx >> 6;
    const int h = rest % Hn;
    const int t = rest / Hn;
    const float* wrow = g_qkvw + (size_t)t * OUTDn + WOFF + h * 3;
    const float g0 = 1.f / (1.f + expf(-wrow[0]));
    const float g1 = 1.f / (1.f + expf(-wrow[1]));
    const float g2 = 1.f / (1.f + expf(-wrow[2]));
    float val = g0 * g_ocmp[idx] + g1 * g_osel[idx] + g2 * g_owin[idx];
    unsigned short hh, ll;
    f32_hl(val, hh, ll);
    unsigned short* p = (unsigned short*)g_a2o + (size_t)idx * 3;
    p[0] = hh; p[1] = hh; p[2] = ll;
}

// ---------------- launch ----------------
extern "C" void kernel_launch(void* const* d_in, const int* in_sizes, int n_in,
                              void* d_out, int out_size) {
    const float* x    = (const float*)d_in[0];
    const float* cosp = (const float*)d_in[1];
    const float* sinp = (const float*)d_in[2];
    const float* Wqkv = (const float*)d_in[3];
    const float* Wo   = (const float*)d_in[4];
    float* out = (float*)d_out;

    cudaFuncSetAttribute(gemm_mma_qkvw, cudaFuncAttributeMaxDynamicSharedMemorySize, GEMM_SMEM);
    cudaFuncSetAttribute(gemm_mma_out,  cudaFuncAttributeMaxDynamicSharedMemorySize, GEMM_SMEM);

    conv_x_kernel<<<(Tn * HIDn + 255) / 256, 256>>>(x);
    {
        dim3 b(32, 32);
        tr_q_kernel<<<dim3(76, 64), b>>>(Wqkv);
        tr_o_kernel<<<dim3(64, 64), b>>>(Wo);
    }
    gemm_mma_qkvw<<<dim3(NPADn / 128, Tn / 128), 512, GEMM_SMEM>>>();
    rope_kernel<<<(Tn * (Hn + HKVn) * Dn + 255) / 256, 256>>>(cosp, sinp);
    pool_kernel<<<(NBn * Gn * Dn + 255) / 256, 256>>>();
    cmp2_kernel<<<dim3(Tn, Gn), 512>>>();
    topk_kernel<<<(Tn * Gn + 255) / 256, 256>>>();
    sel3_kernel<<<dim3(Tn, Gn), 512>>>();
    win4_kernel<<<dim3(Tn, Gn), 512>>>();
    combine_kernel<<<(Tn * Hn * Dn + 255) / 256, 256>>>();
    gemm_mma_out<<<dim3(HIDn / 128, Tn / 128), 512, GEMM_SMEM>>>(out);
}

// round 14
// speedup vs baseline: 1.1205x; 1.1205x over previous
#include <cuda_runtime.h>
#include <cuda_bf16.h>
#include <cstdint>
#include <math.h>

#define Tn    2048
#define HIDn  2048
#define Hn    32
#define HKVn  2
#define Dn    64
#define Gn    2
#define HGn   16
#define BLKn  32
#define NSELn 8
#define WINn  256
#define NBn   64
#define OUTDn 2400
#define NPADn 2432          /* 19*128 */
#define K2n   6144          /* 3x K=2048 : [ah,ah,al] x [bh,bl,bh] */
#define KOFF  (Hn*Dn)
#define VOFF  (KOFF + HKVn*Dn)
#define WOFF  (VOFF + HKVn*Dn)
#define NEGf  (-1e30f)
#define SCALEf 0.125f

// ---------------- scratch ----------------
__device__ float g_qkvw[Tn*OUTDn];
__device__ float g_q[Tn*Hn*Dn];
__device__ float g_k[Tn*HKVn*Dn];
__device__ float g_kcmp[NBn*Gn*Dn];
__device__ float g_vcmp[NBn*Gn*Dn];
__device__ float g_ocmp[Tn*Hn*Dn];
__device__ float g_osel[Tn*Hn*Dn];
__device__ float g_owin[Tn*Hn*Dn];
__device__ int   g_selidx[Tn*Gn*NSELn];
__device__ __align__(16) __nv_bfloat16 g_a2x[(size_t)Tn*K2n];
__device__ __align__(16) __nv_bfloat16 g_a2o[(size_t)Tn*K2n];
__device__ __align__(16) __nv_bfloat16 g_b2q[(size_t)NPADn*K2n];
__device__ __align__(16) __nv_bfloat16 g_b2o[(size_t)HIDn*K2n];

// ---------------- helpers ----------------
__device__ __forceinline__ uint32_t smem_u32(const void* p) {
    uint32_t a;
    asm("{ .reg .u64 t; cvta.to.shared.u64 t, %1; cvt.u32.u64 %0, t; }" : "=r"(a) : "l"(p));
    return a;
}
#define CP_ASYNC16(dst, src) \
    asm volatile("cp.async.cg.shared.global [%0], [%1], 16;" :: "r"(dst), "l"(src) : "memory")
#define CP_COMMIT() asm volatile("cp.async.commit_group;" ::: "memory")
#define CP_WAIT1()  asm volatile("cp.async.wait_group 1;" ::: "memory")
#define CP_WAIT0()  asm volatile("cp.async.wait_group 0;" ::: "memory")

__device__ __forceinline__ void ldsm4(uint32_t &r0, uint32_t &r1, uint32_t &r2, uint32_t &r3,
                                      uint32_t addr) {
    asm volatile("ldmatrix.sync.aligned.m8n8.x4.shared.b16 {%0,%1,%2,%3}, [%4];"
                 : "=r"(r0), "=r"(r1), "=r"(r2), "=r"(r3) : "r"(addr));
}
__device__ __forceinline__ void mma_bf16(float* c, uint32_t a0, uint32_t a1, uint32_t a2,
                                         uint32_t a3, uint32_t b0, uint32_t b1) {
    asm volatile("mma.sync.aligned.m16n8k16.row.col.f32.bf16.bf16.f32 "
                 "{%0,%1,%2,%3}, {%4,%5,%6,%7}, {%8,%9}, {%0,%1,%2,%3};"
                 : "+f"(c[0]), "+f"(c[1]), "+f"(c[2]), "+f"(c[3])
                 : "r"(a0), "r"(a1), "r"(a2), "r"(a3), "r"(b0), "r"(b1));
}

__device__ __forceinline__ float warpMax(float v) {
    #pragma unroll
    for (int o = 16; o > 0; o >>= 1) v = fmaxf(v, __shfl_xor_sync(0xffffffffu, v, o));
    return v;
}
__device__ __forceinline__ float warpSum(float v) {
    #pragma unroll
    for (int o = 16; o > 0; o >>= 1) v += __shfl_xor_sync(0xffffffffu, v, o);
    return v;
}
__device__ __forceinline__ void f32_hl(float v, unsigned short &h, unsigned short &l) {
    __nv_bfloat16 bh = __float2bfloat16(v);
    float r = v - __bfloat162float(bh);
    __nv_bfloat16 bl = __float2bfloat16(r);
    h = __bfloat16_as_ushort(bh);
    l = __bfloat16_as_ushort(bl);
}
__device__ __forceinline__ float dot64_f4(const float4* __restrict__ q4,
                                          const float4* __restrict__ k4) {
    float acc = 0.f;
    #pragma unroll
    for (int i = 0; i < 16; i++) {
        float4 qv = q4[i], kv = k4[i];
        acc = fmaf(qv.x, kv.x, acc);
        acc = fmaf(qv.y, kv.y, acc);
        acc = fmaf(qv.z, kv.z, acc);
        acc = fmaf(qv.w, kv.w, acc);
    }
    return acc;
}

// ---------------- mma.sync split-bf16 GEMM body (unchanged from R13) ----------------
#define SAst 40
#define STAGE_BYTES (128*SAst*2)
#define STAGE_PAIR  (2*STAGE_BYTES)
#define NSTAGE 3
#define GEMM_SMEM (NSTAGE*STAGE_PAIR)
__device__ __forceinline__ void gemm_body(const __nv_bfloat16* __restrict__ A2,
                                          const __nv_bfloat16* __restrict__ B2,
                                          float* __restrict__ C,
                                          int Nvalid, int ldc) {
    extern __shared__ __align__(16) unsigned char smem[];
    const uint32_t sbase = smem_u32(smem);
    const int tid = threadIdx.x;
    const int lane = tid & 31;
    const int warp = tid >> 5;
    const int wm = warp >> 2;
    const int wn = warp & 3;
    const int m0 = blockIdx.y * 128;
    const int n0 = blockIdx.x * 128;

    const int lrow = tid >> 2;
    const int lk   = (tid & 3) * 8;
    const __nv_bfloat16* aG = A2 + (size_t)(m0 + lrow) * K2n + lk;
    const __nv_bfloat16* bG = B2 + (size_t)(n0 + lrow) * K2n + lk;
    const uint32_t wOff = (uint32_t)(lrow * SAst + lk) * 2;

    float acc[2][4][4];
    #pragma unroll
    for (int i = 0; i < 2; i++)
        #pragma unroll
        for (int j = 0; j < 4; j++)
            #pragma unroll
            for (int r = 0; r < 4; r++) acc[i][j][r] = 0.f;

    const int NK = K2n / 32;

    const uint32_t aRow = (uint32_t)(wm * 32 + (lane & 15));
    const uint32_t aColSel = (uint32_t)((lane >> 4) * 8);
    const int ro = lane >> 3;
    const uint32_t bRow = (uint32_t)(wn * 32 + ((ro & 2) ? 8 : 0) + (lane & 7));
    const uint32_t bColSel = (uint32_t)((ro & 1) ? 8 : 0);

    #pragma unroll
    for (int s = 0; s < 2; s++) {
        uint32_t sA = sbase + (uint32_t)s * STAGE_PAIR;
        uint32_t sB = sA + STAGE_BYTES;
        CP_ASYNC16(sA + wOff, aG + (size_t)s * 32);
        CP_ASYNC16(sB + wOff, bG + (size_t)s * 32);
        CP_COMMIT();
    }

    for (int kc = 0; kc < NK; kc++) {
        if (kc + 2 < NK) CP_WAIT1(); else CP_WAIT0();
        __syncthreads();

        if (kc + 2 < NK) {
            uint32_t st = (uint32_t)((kc + 2) % 3) * STAGE_PAIR;
            uint32_t sA = sbase + st;
            uint32_t sB = sA + STAGE_BYTES;
            CP_ASYNC16(sA + wOff, aG + (size_t)(kc + 2) * 32);
            CP_ASYNC16(sB + wOff, bG + (size_t)(kc + 2) * 32);
            CP_COMMIT();
        }

        uint32_t st = (uint32_t)(kc % 3) * STAGE_PAIR;
        uint32_t sA = sbase + st;
        uint32_t sB = sA + STAGE_BYTES;

        #pragma unroll
        for (int s = 0; s < 2; s++) {
            uint32_t af[2][4];
            #pragma unroll
            for (int i = 0; i < 2; i++) {
                uint32_t addr = sA + ((aRow + i * 16) * SAst + s * 16 + aColSel) * 2;
                ldsm4(af[i][0], af[i][1], af[i][2], af[i][3], addr);
            }
            uint32_t bf[4][2];
            #pragma unroll
            for (int j2 = 0; j2 < 2; j2++) {
                uint32_t addr = sB + ((bRow + j2 * 16) * SAst + s * 16 + bColSel) * 2;
                uint32_t r0, r1, r2, r3;
                ldsm4(r0, r1, r2, r3, addr);
                bf[2*j2][0] = r0; bf[2*j2][1] = r1;
                bf[2*j2+1][0] = r2; bf[2*j2+1][1] = r3;
            }
            #pragma unroll
            for (int i = 0; i < 2; i++)
                #pragma unroll
                for (int j = 0; j < 4; j++)
                    mma_bf16(acc[i][j], af[i][0], af[i][1], af[i][2], af[i][3],
                             bf[j][0], bf[j][1]);
        }
    }

    const int rbase = m0 + wm * 32 + (lane >> 2);
    const int cbase = n0 + wn * 32 + (lane & 3) * 2;
    #pragma unroll
    for (int i = 0; i < 2; i++) {
        #pragma unroll
        for (int j = 0; j < 4; j++) {
            int rr = rbase + i * 16;
            int cc = cbase + j * 8;
            if (cc < Nvalid) {
                float* p0 = C + (size_t)rr * ldc + cc;
                p0[0] = acc[i][j][0];
                if (cc + 1 < Nvalid) p0[1] = acc[i][j][1];
                float* p1 = C + (size_t)(rr + 8) * ldc + cc;
                p1[0] = acc[i][j][2];
                if (cc + 1 < Nvalid) p1[1] = acc[i][j][3];
            }
        }
    }
}

__global__ __launch_bounds__(512) void gemm_mma_qkvw() {
    gemm_body(g_a2x, g_b2q, g_qkvw, OUTDn, OUTDn);
}
__global__ __launch_bounds__(512) void gemm_mma_out(float* __restrict__ C) {
    gemm_body(g_a2o, g_b2o, C, HIDn, HIDn);
}

// ---------------- conversions ----------------
__global__ void conv_x_kernel(const float* __restrict__ x) {
    int idx = blockIdx.x * blockDim.x + threadIdx.x;
    if (idx >= Tn * HIDn) return;
    unsigned short h, l;
    f32_hl(x[idx], h, l);
    unsigned short* p = (unsigned short*)g_a2x + (size_t)idx * 3;
    p[0] = h; p[1] = h; p[2] = l;
}
__device__ __forceinline__ void tr_body(const float* __restrict__ W,
                                        __nv_bfloat16* __restrict__ B2,
                                        int Ncols, int Npad) {
    __shared__ float tile[32][33];
    int n = blockIdx.x * 32 + threadIdx.x;
    int k = blockIdx.y * 32 + threadIdx.y;
    tile[threadIdx.y][threadIdx.x] = (n < Ncols) ? W[(size_t)k * Ncols + n] : 0.f;
    __syncthreads();
    int nn = blockIdx.x * 32 + threadIdx.y;
    int kk = blockIdx.y * 32 + threadIdx.x;
    if (nn < Npad) {
        unsigned short h, l;
        f32_hl(tile[threadIdx.x][threadIdx.y], h, l);
        unsigned short* p = (unsigned short*)B2 + (size_t)nn * K2n + (size_t)kk * 3;
        p[0] = h; p[1] = l; p[2] = h;
    }
}
__global__ void tr_q_kernel(const float* __restrict__ W) { tr_body(W, g_b2q, OUTDn, NPADn); }
__global__ void tr_o_kernel(const float* __restrict__ W) { tr_body(W, g_b2o, HIDn, HIDn); }

// ---------------- RoPE ----------------
__global__ void rope_kernel(const float* __restrict__ cosp, const float* __restrict__ sinp) {
    int idx = blockIdx.x * blockDim.x + threadIdx.x;
    const int total = Tn * (Hn + HKVn) * Dn;
    if (idx >= total) return;
    const int d = idx & 63;
    int rest = idx >> 6;
    const int h = rest % (Hn + HKVn);
    const int t = rest / (Hn + HKVn);
    const float c = cosp[t * Dn + d];
    const float s = sinp[t * Dn + d];
    if (h < Hn) {
        const float* row = g_qkvw + (size_t)t * OUTDn + h * Dn;
        float x = row[d];
        float rot = (d < 32) ? -row[d + 32] : row[d - 32];
        g_q[((size_t)t * Hn + h) * Dn + d] = x * c + rot * s;
    } else {
        const int g = h - Hn;
        const float* row = g_qkvw + (size_t)t * OUTDn + KOFF + g * Dn;
        float x = row[d];
        float rot = (d < 32) ? -row[d + 32] : row[d - 32];
        g_k[((size_t)t * HKVn + g) * Dn + d] = x * c + rot * s;
    }
}

// ---------------- mean-pool ----------------
__global__ void pool_kernel() {
    int idx = blockIdx.x * blockDim.x + threadIdx.x;
    if (idx >= NBn * Gn * Dn) return;
    const int d = idx & 63;
    int rest = idx >> 6;
    const int g = rest % Gn;
    const int n = rest / Gn;
    float sk = 0.f, sv = 0.f;
    #pragma unroll 4
    for (int b = 0; b < BLKn; b++) {
        const int t = n * BLKn + b;
        sk += g_k[((size_t)t * HKVn + g) * Dn + d];
        sv += g_qkvw[(size_t)t * OUTDn + VOFF + g * Dn + d];
    }
    g_kcmp[idx] = sk * (1.f / BLKn);
    g_vcmp[idx] = sv * (1.f / BLKn);
}

// ---------------- compressed attention + fused top-8: CTA per (t,g) ----------------
#define KST 68   /* K smem row stride (floats), mult of 4 for float4 */
__global__ __launch_bounds__(512) void cmp3_kernel() {
    const int t = blockIdx.x, g = blockIdx.y;
    const int tid = threadIdx.x, w = tid >> 5, lane = tid & 31;
    __shared__ __align__(16) float kc[NBn][KST];
    __shared__ __align__(16) float vc[NBn][KST];
    __shared__ __align__(16) float qs[HGn][Dn];
    __shared__ float ps[HGn][NBn];

    // float4 fills
    for (int i = tid; i < NBn * 16; i += 512) {
        int n = i >> 4, d4 = i & 15;
        ((float4*)kc[n])[d4] = ((const float4*)(g_kcmp + ((size_t)n * Gn + g) * Dn))[d4];
        ((float4*)vc[n])[d4] = ((const float4*)(g_vcmp + ((size_t)n * Gn + g) * Dn))[d4];
    }
    if (tid < HGn * 16) {
        int hg = tid >> 4, d4 = tid & 15;
        ((float4*)qs[hg])[d4] = ((const float4*)(g_q + ((size_t)t * Hn + g * HGn + hg) * Dn))[d4];
    }
    __syncthreads();

    const int nvis = (t + 1) >> 5;
    const float4* q4 = (const float4*)qs[w];
    float sc[2];
    #pragma unroll
    for (int ii = 0; ii < 2; ii++) {
        const int n = lane + ii * 32;
        sc[ii] = (n < nvis) ? dot64_f4(q4, (const float4*)kc[n]) * SCALEf : NEGf;
    }
    float p0 = 0.f, p1 = 0.f;
    if (nvis > 0) {
        float m = warpMax(fmaxf(sc[0], sc[1]));
        float e0 = expf(sc[0] - m), e1 = expf(sc[1] - m);
        float inv = 1.f / warpSum(e0 + e1);
        p0 = e0 * inv; p1 = e1 * inv;
    }
    ps[w][lane] = p0; ps[w][lane + 32] = p1;
    __syncthreads();

    // V accumulate: this thread owns d = {2*lane, 2*lane+1}
    float a0 = 0.f, a1 = 0.f;
    for (int n = 0; n < nvis; n++) {
        const float p = ps[w][n];
        float2 v = *(const float2*)&vc[n][2 * lane];
        a0 = fmaf(p, v.x, a0);
        a1 = fmaf(p, v.y, a1);
    }
    float* orow = g_ocmp + ((size_t)t * Hn + g * HGn + w) * Dn;
    *(float2*)&orow[2 * lane] = make_float2(a0, a1);

    // warp 0: fused top-8 (exact sequential semantics: max with lowest index on ties)
    if (w == 0) {
        const int tb = t >> 5;
        float v0 = 0.f, v1 = 0.f;
        #pragma unroll
        for (int hg = 0; hg < HGn; hg++) { v0 += ps[hg][lane]; v1 += ps[hg][lane + 32]; }
        if (lane == 0)  v0 += 1e4f;
        if (lane == tb) v0 += 1e4f;
        if (lane + 32 == tb) v1 += 1e4f;
        if (lane > tb)      v0 = NEGf;
        if (lane + 32 > tb) v1 = NEGf;
        int* selp = g_selidx + ((size_t)t * Gn + g) * NSELn;
        #pragma unroll
        for (int i = 0; i < NSELn; i++) {
            float bv = v0; int bi = lane;
            if (v1 > bv) { bv = v1; bi = lane + 32; }
            #pragma unroll
            for (int o = 16; o > 0; o >>= 1) {
                float ov = __shfl_xor_sync(0xffffffffu, bv, o);
                int   oi = __shfl_xor_sync(0xffffffffu, bi, o);
                if (ov > bv || (ov == bv && oi < bi)) { bv = ov; bi = oi; }
            }
            if (lane == 0) selp[i] = bi;
            if (bi == lane)      v0 = -2e30f;
            if (bi == lane + 32) v1 = -2e30f;
        }
    }
}

// ---------------- selection attention: single pass, vectorized ----------------
__global__ __launch_bounds__(512) void sel3_kernel() {
    const int t = blockIdx.x, g = blockIdx.y;
    const int tid = threadIdx.x, w = tid >> 5, lane = tid & 31;
    __shared__ __align__(16) float kb[BLKn][KST];
    __shared__ __align__(16) float vb[BLKn][KST];
    __shared__ __align__(16) float qs[HGn][Dn];
    __shared__ float ps[HGn][32];
    __shared__ int sel[NSELn];

    if (tid < HGn * 16) {
        int hg = tid >> 4, d4 = tid & 15;
        ((float4*)qs[hg])[d4] = ((const float4*)(g_q + ((size_t)t * Hn + g * HGn + hg) * Dn))[d4];
    }
    if (tid < NSELn) sel[tid] = g_selidx[((size_t)t * Gn + g) * NSELn + tid];
    __syncthreads();

    const float4* q4 = (const float4*)qs[w];
    float m = NEGf, l = 0.f, a0 = 0.f, a1 = 0.f;
    for (int i = 0; i < NSELn; i++) {
        const int base = sel[i] * BLKn;
        if (tid < BLKn * 16) {
            int b = tid >> 4, d4 = tid & 15;
            ((float4*)kb[b])[d4] = ((const float4*)(g_k + ((size_t)(base + b) * HKVn + g) * Dn))[d4];
            ((float4*)vb[b])[d4] = ((const float4*)(g_qkvw + (size_t)(base + b) * OUTDn + VOFF + g * Dn))[d4];
        }
        __syncthreads();
        const int pos = base + lane;
        float s = (pos <= t) ? dot64_f4(q4, (const float4*)kb[lane]) * SCALEf : NEGf;
        float mnew = fmaxf(m, warpMax(s));
        float corr = expf(m - mnew);
        float e = (pos <= t) ? expf(s - mnew) : 0.f;
        ps[w][lane] = e;
        __syncwarp();
        l = l * corr + warpSum(e);
        a0 *= corr; a1 *= corr;
        #pragma unroll 8
        for (int b = 0; b < BLKn; b++) {
            const float p = ps[w][b];
            float2 v = *(const float2*)&vb[b][2 * lane];
            a0 = fmaf(p, v.x, a0);
            a1 = fmaf(p, v.y, a1);
        }
        m = mnew;
        __syncthreads();
    }
    float inv = 1.f / l;
    float* orow = g_osel + ((size_t)t * Hn + g * HGn + w) * Dn;
    *(float2*)&orow[2 * lane] = make_float2(a0 * inv, a1 * inv);
}

// ---------------- sliding window: single pass, vectorized ----------------
__global__ __launch_bounds__(512) void win4_kernel() {
    const int t = blockIdx.x, g = blockIdx.y;
    const int tid = threadIdx.x, w = tid >> 5, lane = tid & 31;
    __shared__ __align__(16) float kb[BLKn][KST];
    __shared__ __align__(16) float vb[BLKn][KST];
    __shared__ __align__(16) float qs[HGn][Dn];
    __shared__ float ps[HGn][32];

    if (tid < HGn * 16) {
        int hg = tid >> 4, d4 = tid & 15;
        ((float4*)qs[hg])[d4] = ((const float4*)(g_q + ((size_t)t * Hn + g * HGn + hg) * Dn))[d4];
    }
    __syncthreads();

    const float4* q4 = (const float4*)qs[w];
    const int p0i = t - (WINn - 1);
    float m = NEGf, l = 0.f, a0 = 0.f, a1 = 0.f;
    for (int i = 0; i < 8; i++) {
        const int base = p0i + i * 32;
        if (tid < BLKn * 16) {
            int b = tid >> 4, d4 = tid & 15;
            int row = base + b; if (row < 0) row = 0;
            ((float4*)kb[b])[d4] = ((const float4*)(g_k + ((size_t)row * HKVn + g) * Dn))[d4];
            ((float4*)vb[b])[d4] = ((const float4*)(g_qkvw + (size_t)row * OUTDn + VOFF + g * Dn))[d4];
        }
        __syncthreads();
        const int pos = base + lane;
        float s = (pos >= 0) ? dot64_f4(q4, (const float4*)kb[lane]) * SCALEf : NEGf;
        float mnew = fmaxf(m, warpMax(s));
        float corr = expf(m - mnew);
        float e = (pos >= 0) ? expf(s - mnew) : 0.f;
        ps[w][lane] = e;
        __syncwarp();
        l = l * corr + warpSum(e);
        a0 *= corr; a1 *= corr;
        #pragma unroll 8
        for (int b = 0; b < BLKn; b++) {
            const float p = ps[w][b];
            float2 v = *(const float2*)&vb[b][2 * lane];
            a0 = fmaf(p, v.x, a0);
            a1 = fmaf(p, v.y, a1);
        }
        m = mnew;
        __syncthreads();
    }
    float inv = 1.f / l;
    float* orow = g_owin + ((size_t)t * Hn + g * HGn + w) * Dn;
    *(float2*)&orow[2 * lane] = make_float2(a0 * inv, a1 * inv);
}

// ---------------- gated combine -> 3-term split A operand ----------------
__global__ void combine_kernel() {
    int idx = blockIdx.x * blockDim.x + threadIdx.x;
    if (idx >= Tn * Hn * Dn) return;
    const int d = idx & 63;
    int rest = idx >> 6;
    const int h = rest % Hn;
    const int t = rest / Hn;
    const float* wrow = g_qkvw + (size_t)t * OUTDn + WOFF + h * 3;
    const float g0 = 1.f / (1.f + expf(-wrow[0]));
    const float g1 = 1.f / (1.f + expf(-wrow[1]));
    const float g2 = 1.f / (1.f + expf(-wrow[2]));
    float val = g0 * g_ocmp[idx] + g1 * g_osel[idx] + g2 * g_owin[idx];
    unsigned short hh, ll;
    f32_hl(val, hh, ll);
    unsigned short* p = (unsigned short*)g_a2o + (size_t)idx * 3;
    p[0] = hh; p[1] = hh; p[2] = ll;
}

// ---------------- launch ----------------
extern "C" void kernel_launch(void* const* d_in, const int* in_sizes, int n_in,
                              void* d_out, int out_size) {
    const float* x    = (const float*)d_in[0];
    const float* cosp = (const float*)d_in[1];
    const float* sinp = (const float*)d_in[2];
    const float* Wqkv = (const float*)d_in[3];
    const float* Wo   = (const float*)d_in[4];
    float* out = (float*)d_out;

    cudaFuncSetAttribute(gemm_mma_qkvw, cudaFuncAttributeMaxDynamicSharedMemorySize, GEMM_SMEM);
    cudaFuncSetAttribute(gemm_mma_out,  cudaFuncAttributeMaxDynamicSharedMemorySize, GEMM_SMEM);

    conv_x_kernel<<<(Tn * HIDn + 255) / 256, 256>>>(x);
    {
        dim3 b(32, 32);
        tr_q_kernel<<<dim3(76, 64), b>>>(Wqkv);
        tr_o_kernel<<<dim3(64, 64), b>>>(Wo);
    }
    gemm_mma_qkvw<<<dim3(NPADn / 128, Tn / 128), 512, GEMM_SMEM>>>();
    rope_kernel<<<(Tn * (Hn + HKVn) * Dn + 255) / 256, 256>>>(cosp, sinp);
    pool_kernel<<<(NBn * Gn * Dn + 255) / 256, 256>>>();
    cmp3_kernel<<<dim3(Tn, Gn), 512>>>();
    sel3_kernel<<<dim3(Tn, Gn), 512>>>();
    win4_kernel<<<dim3(Tn, Gn), 512>>>();
    combine_kernel<<<(Tn * Hn * Dn + 255) / 256, 256>>>();
    gemm_mma_out<<<dim3(HIDn / 128, Tn / 128), 512, GEMM_SMEM>>>(out);
}

// round 16
// speedup vs baseline: 1.1394x; 1.0169x over previous
#include <cuda_runtime.h>
#include <cuda_bf16.h>
#include <cstdint>
#include <math.h>

#define Tn    2048
#define HIDn  2048
#define Hn    32
#define HKVn  2
#define Dn    64
#define Gn    2
#define HGn   16
#define BLKn  32
#define NSELn 8
#define WINn  256
#define NBn   64
#define OUTDn 2400
#define NPADn 2432          /* 19*128 */
#define K2n   6144          /* 3x K=2048 : [ah,ah,al] x [bh,bl,bh] */
#define KOFF  (Hn*Dn)
#define VOFF  (KOFF + HKVn*Dn)
#define WOFF  (VOFF + HKVn*Dn)
#define NEGf  (-1e30f)
#define SCALEf 0.125f

// ---------------- scratch ----------------
__device__ float g_qkvw[Tn*OUTDn];
__device__ float g_q[Tn*Hn*Dn];
__device__ float g_k[Tn*HKVn*Dn];
__device__ float g_kcmp[NBn*Gn*Dn];
__device__ float g_vcmp[NBn*Gn*Dn];
__device__ __align__(16) __nv_bfloat16 g_a2x[(size_t)Tn*K2n];
__device__ __align__(16) __nv_bfloat16 g_a2o[(size_t)Tn*K2n];
__device__ __align__(16) __nv_bfloat16 g_b2q[(size_t)NPADn*K2n];
__device__ __align__(16) __nv_bfloat16 g_b2o[(size_t)HIDn*K2n];

// ---------------- helpers ----------------
__device__ __forceinline__ uint32_t smem_u32(const void* p) {
    uint32_t a;
    asm("{ .reg .u64 t; cvta.to.shared.u64 t, %1; cvt.u32.u64 %0, t; }" : "=r"(a) : "l"(p));
    return a;
}
#define CP_ASYNC16(dst, src) \
    asm volatile("cp.async.cg.shared.global [%0], [%1], 16;" :: "r"(dst), "l"(src) : "memory")
#define CP_COMMIT() asm volatile("cp.async.commit_group;" ::: "memory")
#define CP_WAIT1()  asm volatile("cp.async.wait_group 1;" ::: "memory")
#define CP_WAIT0()  asm volatile("cp.async.wait_group 0;" ::: "memory")

__device__ __forceinline__ void ldsm4(uint32_t &r0, uint32_t &r1, uint32_t &r2, uint32_t &r3,
                                      uint32_t addr) {
    asm volatile("ldmatrix.sync.aligned.m8n8.x4.shared.b16 {%0,%1,%2,%3}, [%4];"
                 : "=r"(r0), "=r"(r1), "=r"(r2), "=r"(r3) : "r"(addr));
}
__device__ __forceinline__ void mma_bf16(float* c, uint32_t a0, uint32_t a1, uint32_t a2,
                                         uint32_t a3, uint32_t b0, uint32_t b1) {
    asm volatile("mma.sync.aligned.m16n8k16.row.col.f32.bf16.bf16.f32 "
                 "{%0,%1,%2,%3}, {%4,%5,%6,%7}, {%8,%9}, {%0,%1,%2,%3};"
                 : "+f"(c[0]), "+f"(c[1]), "+f"(c[2]), "+f"(c[3])
                 : "r"(a0), "r"(a1), "r"(a2), "r"(a3), "r"(b0), "r"(b1));
}

__device__ __forceinline__ float warpMax(float v) {
    #pragma unroll
    for (int o = 16; o > 0; o >>= 1) v = fmaxf(v, __shfl_xor_sync(0xffffffffu, v, o));
    return v;
}
__device__ __forceinline__ float warpSum(float v) {
    #pragma unroll
    for (int o = 16; o > 0; o >>= 1) v += __shfl_xor_sync(0xffffffffu, v, o);
    return v;
}
__device__ __forceinline__ void f32_hl(float v, unsigned short &h, unsigned short &l) {
    __nv_bfloat16 bh = __float2bfloat16(v);
    float r = v - __bfloat162float(bh);
    __nv_bfloat16 bl = __float2bfloat16(r);
    h = __bfloat16_as_ushort(bh);
    l = __bfloat16_as_ushort(bl);
}
__device__ __forceinline__ float dot64_f4(const float4* __restrict__ q4,
                                          const float4* __restrict__ k4) {
    float acc = 0.f;
    #pragma unroll
    for (int i = 0; i < 16; i++) {
        float4 qv = q4[i], kv = k4[i];
        acc = fmaf(qv.x, kv.x, acc);
        acc = fmaf(qv.y, kv.y, acc);
        acc = fmaf(qv.z, kv.z, acc);
        acc = fmaf(qv.w, kv.w, acc);
    }
    return acc;
}

// ---------------- mma.sync split-bf16 GEMM body (unchanged) ----------------
#define SAst 40
#define STAGE_BYTES (128*SAst*2)
#define STAGE_PAIR  (2*STAGE_BYTES)
#define NSTAGE 3
#define GEMM_SMEM (NSTAGE*STAGE_PAIR)
__device__ __forceinline__ void gemm_body(const __nv_bfloat16* __restrict__ A2,
                                          const __nv_bfloat16* __restrict__ B2,
                                          float* __restrict__ C,
                                          int Nvalid, int ldc) {
    extern __shared__ __align__(16) unsigned char smem[];
    const uint32_t sbase = smem_u32(smem);
    const int tid = threadIdx.x;
    const int lane = tid & 31;
    const int warp = tid >> 5;
    const int wm = warp >> 2;
    const int wn = warp & 3;
    const int m0 = blockIdx.y * 128;
    const int n0 = blockIdx.x * 128;

    const int lrow = tid >> 2;
    const int lk   = (tid & 3) * 8;
    const __nv_bfloat16* aG = A2 + (size_t)(m0 + lrow) * K2n + lk;
    const __nv_bfloat16* bG = B2 + (size_t)(n0 + lrow) * K2n + lk;
    const uint32_t wOff = (uint32_t)(lrow * SAst + lk) * 2;

    float acc[2][4][4];
    #pragma unroll
    for (int i = 0; i < 2; i++)
        #pragma unroll
        for (int j = 0; j < 4; j++)
            #pragma unroll
            for (int r = 0; r < 4; r++) acc[i][j][r] = 0.f;

    const int NK = K2n / 32;

    const uint32_t aRow = (uint32_t)(wm * 32 + (lane & 15));
    const uint32_t aColSel = (uint32_t)((lane >> 4) * 8);
    const int ro = lane >> 3;
    const uint32_t bRow = (uint32_t)(wn * 32 + ((ro & 2) ? 8 : 0) + (lane & 7));
    const uint32_t bColSel = (uint32_t)((ro & 1) ? 8 : 0);

    #pragma unroll
    for (int s = 0; s < 2; s++) {
        uint32_t sA = sbase + (uint32_t)s * STAGE_PAIR;
        uint32_t sB = sA + STAGE_BYTES;
        CP_ASYNC16(sA + wOff, aG + (size_t)s * 32);
        CP_ASYNC16(sB + wOff, bG + (size_t)s * 32);
        CP_COMMIT();
    }

    for (int kc = 0; kc < NK; kc++) {
        if (kc + 2 < NK) CP_WAIT1(); else CP_WAIT0();
        __syncthreads();

        if (kc + 2 < NK) {
            uint32_t st = (uint32_t)((kc + 2) % 3) * STAGE_PAIR;
            uint32_t sA = sbase + st;
            uint32_t sB = sA + STAGE_BYTES;
            CP_ASYNC16(sA + wOff, aG + (size_t)(kc + 2) * 32);
            CP_ASYNC16(sB + wOff, bG + (size_t)(kc + 2) * 32);
            CP_COMMIT();
        }

        uint32_t st = (uint32_t)(kc % 3) * STAGE_PAIR;
        uint32_t sA = sbase + st;
        uint32_t sB = sA + STAGE_BYTES;

        #pragma unroll
        for (int s = 0; s < 2; s++) {
            uint32_t af[2][4];
            #pragma unroll
            for (int i = 0; i < 2; i++) {
                uint32_t addr = sA + ((aRow + i * 16) * SAst + s * 16 + aColSel) * 2;
                ldsm4(af[i][0], af[i][1], af[i][2], af[i][3], addr);
            }
            uint32_t bf[4][2];
            #pragma unroll
            for (int j2 = 0; j2 < 2; j2++) {
                uint32_t addr = sB + ((bRow + j2 * 16) * SAst + s * 16 + bColSel) * 2;
                uint32_t r0, r1, r2, r3;
                ldsm4(r0, r1, r2, r3, addr);
                bf[2*j2][0] = r0; bf[2*j2][1] = r1;
                bf[2*j2+1][0] = r2; bf[2*j2+1][1] = r3;
            }
            #pragma unroll
            for (int i = 0; i < 2; i++)
                #pragma unroll
                for (int j = 0; j < 4; j++)
                    mma_bf16(acc[i][j], af[i][0], af[i][1], af[i][2], af[i][3],
                             bf[j][0], bf[j][1]);
        }
    }

    const int rbase = m0 + wm * 32 + (lane >> 2);
    const int cbase = n0 + wn * 32 + (lane & 3) * 2;
    #pragma unroll
    for (int i = 0; i < 2; i++) {
        #pragma unroll
        for (int j = 0; j < 4; j++) {
            int rr = rbase + i * 16;
            int cc = cbase + j * 8;
            if (cc < Nvalid) {
                float* p0 = C + (size_t)rr * ldc + cc;
                p0[0] = acc[i][j][0];
                if (cc + 1 < Nvalid) p0[1] = acc[i][j][1];
                float* p1 = C + (size_t)(rr + 8) * ldc + cc;
                p1[0] = acc[i][j][2];
                if (cc + 1 < Nvalid) p1[1] = acc[i][j][3];
            }
        }
    }
}

__global__ __launch_bounds__(512) void gemm_mma_qkvw() {
    gemm_body(g_a2x, g_b2q, g_qkvw, OUTDn, OUTDn);
}
__global__ __launch_bounds__(512) void gemm_mma_out(float* __restrict__ C) {
    gemm_body(g_a2o, g_b2o, C, HIDn, HIDn);
}

// ---------------- conversions ----------------
__global__ void conv_x_kernel(const float* __restrict__ x) {
    int idx = blockIdx.x * blockDim.x + threadIdx.x;
    if (idx >= Tn * HIDn) return;
    unsigned short h, l;
    f32_hl(x[idx], h, l);
    unsigned short* p = (unsigned short*)g_a2x + (size_t)idx * 3;
    p[0] = h; p[1] = h; p[2] = l;
}
__device__ __forceinline__ void tr_body(const float* __restrict__ W,
                                        __nv_bfloat16* __restrict__ B2,
                                        int Ncols, int Npad) {
    __shared__ float tile[32][33];
    int n = blockIdx.x * 32 + threadIdx.x;
    int k = blockIdx.y * 32 + threadIdx.y;
    tile[threadIdx.y][threadIdx.x] = (n < Ncols) ? W[(size_t)k * Ncols + n] : 0.f;
    __syncthreads();
    int nn = blockIdx.x * 32 + threadIdx.y;
    int kk = blockIdx.y * 32 + threadIdx.x;
    if (nn < Npad) {
        unsigned short h, l;
        f32_hl(tile[threadIdx.x][threadIdx.y], h, l);
        unsigned short* p = (unsigned short*)B2 + (size_t)nn * K2n + (size_t)kk * 3;
        p[0] = h; p[1] = l; p[2] = h;
    }
}
__global__ void tr_q_kernel(const float* __restrict__ W) { tr_body(W, g_b2q, OUTDn, NPADn); }
__global__ void tr_o_kernel(const float* __restrict__ W) { tr_body(W, g_b2o, HIDn, HIDn); }

// ---------------- RoPE ----------------
__global__ void rope_kernel(const float* __restrict__ cosp, const float* __restrict__ sinp) {
    int idx = blockIdx.x * blockDim.x + threadIdx.x;
    const int total = Tn * (Hn + HKVn) * Dn;
    if (idx >= total) return;
    const int d = idx & 63;
    int rest = idx >> 6;
    const int h = rest % (Hn + HKVn);
    const int t = rest / (Hn + HKVn);
    const float c = cosp[t * Dn + d];
    const float s = sinp[t * Dn + d];
    if (h < Hn) {
        const float* row = g_qkvw + (size_t)t * OUTDn + h * Dn;
        float x = row[d];
        float rot = (d < 32) ? -row[d + 32] : row[d - 32];
        g_q[((size_t)t * Hn + h) * Dn + d] = x * c + rot * s;
    } else {
        const int g = h - Hn;
        const float* row = g_qkvw + (size_t)t * OUTDn + KOFF + g * Dn;
        float x = row[d];
        float rot = (d < 32) ? -row[d + 32] : row[d - 32];
        g_k[((size_t)t * HKVn + g) * Dn + d] = x * c + rot * s;
    }
}

// ---------------- mean-pool ----------------
__global__ void pool_kernel() {
    int idx = blockIdx.x * blockDim.x + threadIdx.x;
    if (idx >= NBn * Gn * Dn) return;
    const int d = idx & 63;
    int rest = idx >> 6;
    const int g = rest % Gn;
    const int n = rest / Gn;
    float sk = 0.f, sv = 0.f;
    #pragma unroll 4
    for (int b = 0; b < BLKn; b++) {
        const int t = n * BLKn + b;
        sk += g_k[((size_t)t * HKVn + g) * Dn + d];
        sv += g_qkvw[(size_t)t * OUTDn + VOFF + g * Dn + d];
    }
    g_kcmp[idx] = sk * (1.f / BLKn);
    g_vcmp[idx] = sv * (1.f / BLKn);
}

// ---------------- FUSED attention: cmp + top8 + sel + win + combine, CTA per (t,g) ----------------
#define KST 68
__global__ __launch_bounds__(512) void att_kernel() {
    const int t = blockIdx.x, g = blockIdx.y;
    const int tid = threadIdx.x, w = tid >> 5, lane = tid & 31;
    __shared__ __align__(16) float kc[NBn][KST];   // cmp K (rows 0-31 reused as chunk K)
    __shared__ __align__(16) float vc[NBn][KST];   // cmp V (rows 0-31 reused as chunk V)
    __shared__ __align__(16) float qs[HGn][Dn];
    __shared__ float ps[HGn][NBn];
    __shared__ int sel[NSELn];

    // ---- load q tile + pooled K/V ----
    for (int i = tid; i < NBn * 16; i += 512) {
        int n = i >> 4, d4 = i & 15;
        ((float4*)kc[n])[d4] = ((const float4*)(g_kcmp + ((size_t)n * Gn + g) * Dn))[d4];
        ((float4*)vc[n])[d4] = ((const float4*)(g_vcmp + ((size_t)n * Gn + g) * Dn))[d4];
    }
    if (tid < HGn * 16) {
        int hg = tid >> 4, d4 = tid & 15;
        ((float4*)qs[hg])[d4] = ((const float4*)(g_q + ((size_t)t * Hn + g * HGn + hg) * Dn))[d4];
    }
    __syncthreads();

    const float4* q4 = (const float4*)qs[w];

    // ---- compressed branch ----
    const int nvis = (t + 1) >> 5;
    float sc0 = (lane < nvis)      ? dot64_f4(q4, (const float4*)kc[lane])      * SCALEf : NEGf;
    float sc1 = (lane + 32 < nvis) ? dot64_f4(q4, (const float4*)kc[lane + 32]) * SCALEf : NEGf;
    float p0 = 0.f, p1 = 0.f;
    if (nvis > 0) {
        float m = warpMax(fmaxf(sc0, sc1));
        float e0 = expf(sc0 - m), e1 = expf(sc1 - m);
        float inv = 1.f / warpSum(e0 + e1);
        p0 = e0 * inv; p1 = e1 * inv;
    }
    ps[w][lane] = p0; ps[w][lane + 32] = p1;
    __syncthreads();

    float c0 = 0.f, c1 = 0.f;    // o_cmp for d = {2lane, 2lane+1}
    for (int n = 0; n < nvis; n++) {
        const float p = ps[w][n];
        float2 v = *(const float2*)&vc[n][2 * lane];
        c0 = fmaf(p, v.x, c0);
        c1 = fmaf(p, v.y, c1);
    }

    // ---- fused top-8 (warp 0; exact lowest-index-on-ties semantics) ----
    if (w == 0) {
        const int tb = t >> 5;
        float v0 = 0.f, v1 = 0.f;
        #pragma unroll
        for (int hg = 0; hg < HGn; hg++) { v0 += ps[hg][lane]; v1 += ps[hg][lane + 32]; }
        if (lane == 0)  v0 += 1e4f;
        if (lane == tb) v0 += 1e4f;
        if (lane + 32 == tb) v1 += 1e4f;
        if (lane > tb)      v0 = NEGf;
        if (lane + 32 > tb) v1 = NEGf;
        #pragma unroll
        for (int i = 0; i < NSELn; i++) {
            float bv = v0; int bi = lane;
            if (v1 > bv) { bv = v1; bi = lane + 32; }
            #pragma unroll
            for (int o = 16; o > 0; o >>= 1) {
                float ov = __shfl_xor_sync(0xffffffffu, bv, o);
                int   oi = __shfl_xor_sync(0xffffffffu, bi, o);
                if (ov > bv || (ov == bv && oi < bi)) { bv = ov; bi = oi; }
            }
            if (lane == 0) sel[i] = bi;
            if (bi == lane)      v0 = -2e30f;
            if (bi == lane + 32) v1 = -2e30f;
        }
    }
    __syncthreads();   // sel visible; kc/vc reads done -> safe to overwrite rows 0-31

    // ---- selection branch (single pass, online softmax) ----
    float m = NEGf, l = 0.f, s0 = 0.f, s1 = 0.f;
    for (int i = 0; i < NSELn; i++) {
        const int base = sel[i] * BLKn;
        if (tid < BLKn * 16) {
            int b = tid >> 4, d4 = tid & 15;
            ((float4*)kc[b])[d4] = ((const float4*)(g_k + ((size_t)(base + b) * HKVn + g) * Dn))[d4];
            ((float4*)vc[b])[d4] = ((const float4*)(g_qkvw + (size_t)(base + b) * OUTDn + VOFF + g * Dn))[d4];
        }
        __syncthreads();
        const int pos = base + lane;
        float s = (pos <= t) ? dot64_f4(q4, (const float4*)kc[lane]) * SCALEf : NEGf;
        float mnew = fmaxf(m, warpMax(s));
        float corr = expf(m - mnew);
        float e = (pos <= t) ? expf(s - mnew) : 0.f;
        ps[w][lane] = e;
        __syncwarp();
        l = l * corr + warpSum(e);
        s0 *= corr; s1 *= corr;
        #pragma unroll 8
        for (int b = 0; b < BLKn; b++) {
            const float p = ps[w][b];
            float2 v = *(const float2*)&vc[b][2 * lane];
            s0 = fmaf(p, v.x, s0);
            s1 = fmaf(p, v.y, s1);
        }
        m = mnew;
        __syncthreads();
    }
    {
        float inv = 1.f / l;
        s0 *= inv; s1 *= inv;
    }

    // ---- sliding-window branch (single pass, online softmax) ----
    const int p0i = t - (WINn - 1);
    float wm_ = NEGf, wl = 0.f, w0 = 0.f, w1 = 0.f;
    for (int i = 0; i < 8; i++) {
        const int base = p0i + i * 32;
        if (tid < BLKn * 16) {
            int b = tid >> 4, d4 = tid & 15;
            int row = base + b; if (row < 0) row = 0;
            ((float4*)kc[b])[d4] = ((const float4*)(g_k + ((size_t)row * HKVn + g) * Dn))[d4];
            ((float4*)vc[b])[d4] = ((const float4*)(g_qkvw + (size_t)row * OUTDn + VOFF + g * Dn))[d4];
        }
        __syncthreads();
        const int pos = base + lane;
        float s = (pos >= 0) ? dot64_f4(q4, (const float4*)kc[lane]) * SCALEf : NEGf;
        float mnew = fmaxf(wm_, warpMax(s));
        float corr = expf(wm_ - mnew);
        float e = (pos >= 0) ? expf(s - mnew) : 0.f;
        ps[w][lane] = e;
        __syncwarp();
        wl = wl * corr + warpSum(e);
        w0 *= corr; w1 *= corr;
        #pragma unroll 8
        for (int b = 0; b < BLKn; b++) {
            const float p = ps[w][b];
            float2 v = *(const float2*)&vc[b][2 * lane];
            w0 = fmaf(p, v.x, w0);
            w1 = fmaf(p, v.y, w1);
        }
        wm_ = mnew;
        __syncthreads();
    }
    {
        float inv = 1.f / wl;
        w0 *= inv; w1 *= inv;
    }

    // ---- gated combine -> packed 3-term bf16 operand ----
    const int h = g * HGn + w;
    const float* wrow = g_qkvw + (size_t)t * OUTDn + WOFF + h * 3;
    const float ga = 1.f / (1.f + expf(-wrow[0]));
    const float gb = 1.f / (1.f + expf(-wrow[1]));
    const float gc = 1.f / (1.f + expf(-wrow[2]));
    float o0 = ga * c0 + gb * s0 + gc * w0;
    float o1 = ga * c1 + gb * s1 + gc * w1;
    unsigned short h0, l0, h1, l1;
    f32_hl(o0, h0, l0);
    f32_hl(o1, h1, l1);
    const size_t idx = ((size_t)t * Hn + h) * Dn + 2 * lane;   // element index
    uint32_t* p = (uint32_t*)((unsigned short*)g_a2o + idx * 3);
    p[0] = (uint32_t)h0 | ((uint32_t)h0 << 16);
    p[1] = (uint32_t)l0 | ((uint32_t)h1 << 16);
    p[2] = (uint32_t)h1 | ((uint32_t)l1 << 16);
}

// ---------------- launch ----------------
extern "C" void kernel_launch(void* const* d_in, const int* in_sizes, int n_in,
                              void* d_out, int out_size) {
    const float* x    = (const float*)d_in[0];
    const float* cosp = (const float*)d_in[1];
    const float* sinp = (const float*)d_in[2];
    const float* Wqkv = (const float*)d_in[3];
    const float* Wo   = (const float*)d_in[4];
    float* out = (float*)d_out;

    cudaFuncSetAttribute(gemm_mma_qkvw, cudaFuncAttributeMaxDynamicSharedMemorySize, GEMM_SMEM);
    cudaFuncSetAttribute(gemm_mma_out,  cudaFuncAttributeMaxDynamicSharedMemorySize, GEMM_SMEM);

    conv_x_kernel<<<(Tn * HIDn + 255) / 256, 256>>>(x);
    {
        dim3 b(32, 32);
        tr_q_kernel<<<dim3(76, 64), b>>>(Wqkv);
        tr_o_kernel<<<dim3(64, 64), b>>>(Wo);
    }
    gemm_mma_qkvw<<<dim3(NPADn / 128, Tn / 128), 512, GEMM_SMEM>>>();
    rope_kernel<<<(Tn * (Hn + HKVn) * Dn + 255) / 256, 256>>>(cosp, sinp);
    pool_kernel<<<(NBn * Gn * Dn + 255) / 256, 256>>>();
    att_kernel<<<dim3(Tn, Gn), 512>>>();
    gemm_mma_out<<<dim3(HIDn / 128, Tn / 128), 512, GEMM_SMEM>>>(out);
}

// round 17
// speedup vs baseline: 1.4763x; 1.2957x over previous
#include <cuda_runtime.h>
#include <cuda_bf16.h>
#include <cstdint>
#include <math.h>

#define Tn    2048
#define HIDn  2048
#define Hn    32
#define HKVn  2
#define Dn    64
#define Gn    2
#define HGn   16
#define BLKn  32
#define NSELn 8
#define WINn  256
#define NBn   64
#define OUTDn 2400
#define NPADn 2432
#define K2n   6144
#define KOFF  (Hn*Dn)
#define VOFF  (KOFF + HKVn*Dn)
#define WOFF  (VOFF + HKVn*Dn)
#define NEGf  (-1e30f)
#define SCALEf 0.125f

// ---------------- scratch ----------------
__device__ float g_qkvw[Tn*OUTDn];
__device__ float g_q[Tn*Hn*Dn];
__device__ float g_k[Tn*HKVn*Dn];
__device__ float g_kcmp[NBn*Gn*Dn];
__device__ float g_vcmp[NBn*Gn*Dn];
__device__ __align__(16) __nv_bfloat16 g_a2x[(size_t)Tn*K2n];
__device__ __align__(16) __nv_bfloat16 g_a2o[(size_t)Tn*K2n];
__device__ __align__(16) __nv_bfloat16 g_b2q[(size_t)NPADn*K2n];
__device__ __align__(16) __nv_bfloat16 g_b2o[(size_t)HIDn*K2n];

// ---------------- helpers ----------------
__device__ __forceinline__ uint32_t smem_u32(const void* p) {
    uint32_t a;
    asm("{ .reg .u64 t; cvta.to.shared.u64 t, %1; cvt.u32.u64 %0, t; }" : "=r"(a) : "l"(p));
    return a;
}
#define CP_ASYNC16(dst, src) \
    asm volatile("cp.async.cg.shared.global [%0], [%1], 16;" :: "r"(dst), "l"(src) : "memory")
#define CP_COMMIT() asm volatile("cp.async.commit_group;" ::: "memory")
#define CP_WAIT1()  asm volatile("cp.async.wait_group 1;" ::: "memory")
#define CP_WAIT0()  asm volatile("cp.async.wait_group 0;" ::: "memory")

__device__ __forceinline__ void ldsm4(uint32_t &r0, uint32_t &r1, uint32_t &r2, uint32_t &r3,
                                      uint32_t addr) {
    asm volatile("ldmatrix.sync.aligned.m8n8.x4.shared.b16 {%0,%1,%2,%3}, [%4];"
                 : "=r"(r0), "=r"(r1), "=r"(r2), "=r"(r3) : "r"(addr));
}
__device__ __forceinline__ void mma_bf16(float* c, uint32_t a0, uint32_t a1, uint32_t a2,
                                         uint32_t a3, uint32_t b0, uint32_t b1) {
    asm volatile("mma.sync.aligned.m16n8k16.row.col.f32.bf16.bf16.f32 "
                 "{%0,%1,%2,%3}, {%4,%5,%6,%7}, {%8,%9}, {%0,%1,%2,%3};"
                 : "+f"(c[0]), "+f"(c[1]), "+f"(c[2]), "+f"(c[3])
                 : "r"(a0), "r"(a1), "r"(a2), "r"(a3), "r"(b0), "r"(b1));
}

__device__ __forceinline__ float warpMax(float v) {
    #pragma unroll
    for (int o = 16; o > 0; o >>= 1) v = fmaxf(v, __shfl_xor_sync(0xffffffffu, v, o));
    return v;
}
__device__ __forceinline__ float warpSum(float v) {
    #pragma unroll
    for (int o = 16; o > 0; o >>= 1) v += __shfl_xor_sync(0xffffffffu, v, o);
    return v;
}
__device__ __forceinline__ void f32_hl(float v, unsigned short &h, unsigned short &l) {
    __nv_bfloat16 bh = __float2bfloat16(v);
    float r = v - __bfloat162float(bh);
    __nv_bfloat16 bl = __float2bfloat16(r);
    h = __bfloat16_as_ushort(bh);
    l = __bfloat16_as_ushort(bl);
}

// ---------------- mma.sync split-bf16 GEMM body (unchanged) ----------------
#define SAst 40
#define STAGE_BYTES (128*SAst*2)
#define STAGE_PAIR  (2*STAGE_BYTES)
#define NSTAGE 3
#define GEMM_SMEM (NSTAGE*STAGE_PAIR)
__device__ __forceinline__ void gemm_body(const __nv_bfloat16* __restrict__ A2,
                                          const __nv_bfloat16* __restrict__ B2,
                                          float* __restrict__ C,
                                          int Nvalid, int ldc) {
    extern __shared__ __align__(16) unsigned char smem[];
    const uint32_t sbase = smem_u32(smem);
    const int tid = threadIdx.x;
    const int lane = tid & 31;
    const int warp = tid >> 5;
    const int wm = warp >> 2;
    const int wn = warp & 3;
    const int m0 = blockIdx.y * 128;
    const int n0 = blockIdx.x * 128;

    const int lrow = tid >> 2;
    const int lk   = (tid & 3) * 8;
    const __nv_bfloat16* aG = A2 + (size_t)(m0 + lrow) * K2n + lk;
    const __nv_bfloat16* bG = B2 + (size_t)(n0 + lrow) * K2n + lk;
    const uint32_t wOff = (uint32_t)(lrow * SAst + lk) * 2;

    float acc[2][4][4];
    #pragma unroll
    for (int i = 0; i < 2; i++)
        #pragma unroll
        for (int j = 0; j < 4; j++)
            #pragma unroll
            for (int r = 0; r < 4; r++) acc[i][j][r] = 0.f;

    const int NK = K2n / 32;

    const uint32_t aRow = (uint32_t)(wm * 32 + (lane & 15));
    const uint32_t aColSel = (uint32_t)((lane >> 4) * 8);
    const int ro = lane >> 3;
    const uint32_t bRow = (uint32_t)(wn * 32 + ((ro & 2) ? 8 : 0) + (lane & 7));
    const uint32_t bColSel = (uint32_t)((ro & 1) ? 8 : 0);

    #pragma unroll
    for (int s = 0; s < 2; s++) {
        uint32_t sA = sbase + (uint32_t)s * STAGE_PAIR;
        uint32_t sB = sA + STAGE_BYTES;
        CP_ASYNC16(sA + wOff, aG + (size_t)s * 32);
        CP_ASYNC16(sB + wOff, bG + (size_t)s * 32);
        CP_COMMIT();
    }

    for (int kc = 0; kc < NK; kc++) {
        if (kc + 2 < NK) CP_WAIT1(); else CP_WAIT0();
        __syncthreads();

        if (kc + 2 < NK) {
            uint32_t st = (uint32_t)((kc + 2) % 3) * STAGE_PAIR;
            uint32_t sA = sbase + st;
            uint32_t sB = sA + STAGE_BYTES;
            CP_ASYNC16(sA + wOff, aG + (size_t)(kc + 2) * 32);
            CP_ASYNC16(sB + wOff, bG + (size_t)(kc + 2) * 32);
            CP_COMMIT();
        }

        uint32_t st = (uint32_t)(kc % 3) * STAGE_PAIR;
        uint32_t sA = sbase + st;
        uint32_t sB = sA + STAGE_BYTES;

        #pragma unroll
        for (int s = 0; s < 2; s++) {
            uint32_t af[2][4];
            #pragma unroll
            for (int i = 0; i < 2; i++) {
                uint32_t addr = sA + ((aRow + i * 16) * SAst + s * 16 + aColSel) * 2;
                ldsm4(af[i][0], af[i][1], af[i][2], af[i][3], addr);
            }
            uint32_t bf[4][2];
            #pragma unroll
            for (int j2 = 0; j2 < 2; j2++) {
                uint32_t addr = sB + ((bRow + j2 * 16) * SAst + s * 16 + bColSel) * 2;
                uint32_t r0, r1, r2, r3;
                ldsm4(r0, r1, r2, r3, addr);
                bf[2*j2][0] = r0; bf[2*j2][1] = r1;
                bf[2*j2+1][0] = r2; bf[2*j2+1][1] = r3;
            }
            #pragma unroll
            for (int i = 0; i < 2; i++)
                #pragma unroll
                for (int j = 0; j < 4; j++)
                    mma_bf16(acc[i][j], af[i][0], af[i][1], af[i][2], af[i][3],
                             bf[j][0], bf[j][1]);
        }
    }

    const int rbase = m0 + wm * 32 + (lane >> 2);
    const int cbase = n0 + wn * 32 + (lane & 3) * 2;
    #pragma unroll
    for (int i = 0; i < 2; i++) {
        #pragma unroll
        for (int j = 0; j < 4; j++) {
            int rr = rbase + i * 16;
            int cc = cbase + j * 8;
            if (cc < Nvalid) {
                float* p0 = C + (size_t)rr * ldc + cc;
                p0[0] = acc[i][j][0];
                if (cc + 1 < Nvalid) p0[1] = acc[i][j][1];
                float* p1 = C + (size_t)(rr + 8) * ldc + cc;
                p1[0] = acc[i][j][2];
                if (cc + 1 < Nvalid) p1[1] = acc[i][j][3];
            }
        }
    }
}

__global__ __launch_bounds__(512) void gemm_mma_qkvw() {
    gemm_body(g_a2x, g_b2q, g_qkvw, OUTDn, OUTDn);
}
__global__ __launch_bounds__(512) void gemm_mma_out(float* __restrict__ C) {
    gemm_body(g_a2o, g_b2o, C, HIDn, HIDn);
}

// ---------------- conversions ----------------
__global__ void conv_x_kernel(const float* __restrict__ x) {
    int idx = blockIdx.x * blockDim.x + threadIdx.x;
    if (idx >= Tn * HIDn) return;
    unsigned short h, l;
    f32_hl(x[idx], h, l);
    unsigned short* p = (unsigned short*)g_a2x + (size_t)idx * 3;
    p[0] = h; p[1] = h; p[2] = l;
}
__device__ __forceinline__ void tr_body(const float* __restrict__ W,
                                        __nv_bfloat16* __restrict__ B2,
                                        int Ncols, int Npad) {
    __shared__ float tile[32][33];
    int n = blockIdx.x * 32 + threadIdx.x;
    int k = blockIdx.y * 32 + threadIdx.y;
    tile[threadIdx.y][threadIdx.x] = (n < Ncols) ? W[(size_t)k * Ncols + n] : 0.f;
    __syncthreads();
    int nn = blockIdx.x * 32 + threadIdx.y;
    int kk = blockIdx.y * 32 + threadIdx.x;
    if (nn < Npad) {
        unsigned short h, l;
        f32_hl(tile[threadIdx.x][threadIdx.y], h, l);
        unsigned short* p = (unsigned short*)B2 + (size_t)nn * K2n + (size_t)kk * 3;
        p[0] = h; p[1] = l; p[2] = h;
    }
}
__global__ void tr_q_kernel(const float* __restrict__ W) { tr_body(W, g_b2q, OUTDn, NPADn); }
__global__ void tr_o_kernel(const float* __restrict__ W) { tr_body(W, g_b2o, HIDn, HIDn); }

// ---------------- RoPE ----------------
__global__ void rope_kernel(const float* __restrict__ cosp, const float* __restrict__ sinp) {
    int idx = blockIdx.x * blockDim.x + threadIdx.x;
    const int total = Tn * (Hn + HKVn) * Dn;
    if (idx >= total) return;
    const int d = idx & 63;
    int rest = idx >> 6;
    const int h = rest % (Hn + HKVn);
    const int t = rest / (Hn + HKVn);
    const float c = cosp[t * Dn + d];
    const float s = sinp[t * Dn + d];
    if (h < Hn) {
        const float* row = g_qkvw + (size_t)t * OUTDn + h * Dn;
        float x = row[d];
        float rot = (d < 32) ? -row[d + 32] : row[d - 32];
        g_q[((size_t)t * Hn + h) * Dn + d] = x * c + rot * s;
    } else {
        const int g = h - Hn;
        const float* row = g_qkvw + (size_t)t * OUTDn + KOFF + g * Dn;
        float x = row[d];
        float rot = (d < 32) ? -row[d + 32] : row[d - 32];
        g_k[((size_t)t * HKVn + g) * Dn + d] = x * c + rot * s;
    }
}

// ---------------- mean-pool ----------------
__global__ void pool_kernel() {
    int idx = blockIdx.x * blockDim.x + threadIdx.x;
    if (idx >= NBn * Gn * Dn) return;
    const int d = idx & 63;
    int rest = idx >> 6;
    const int g = rest % Gn;
    const int n = rest / Gn;
    float sk = 0.f, sv = 0.f;
    #pragma unroll 4
    for (int b = 0; b < BLKn; b++) {
        const int t = n * BLKn + b;
        sk += g_k[((size_t)t * HKVn + g) * Dn + d];
        sv += g_qkvw[(size_t)t * OUTDn + VOFF + g * Dn + d];
    }
    g_kcmp[idx] = sk * (1.f / BLKn);
    g_vcmp[idx] = sv * (1.f / BLKn);
}

// ---------------- FUSED attention, 4 heads per warp, CTA per (t,g), 128 threads ----------------
#define KST 68
#define HPW 4      /* heads per warp */
#define NWA 4      /* warps */
__global__ __launch_bounds__(128) void att_kernel() {
    const int t = blockIdx.x, g = blockIdx.y;
    const int tid = threadIdx.x, w = tid >> 5, lane = tid & 31;
    __shared__ __align__(16) float kc[NBn][KST];
    __shared__ __align__(16) float vc[NBn][KST];
    __shared__ __align__(16) float qs[HGn][Dn];
    __shared__ float ps[HGn][NBn];
    __shared__ int sel[NSELn];

    // ---- load q tile + pooled K/V ----
    for (int i = tid; i < NBn * 16; i += 128) {
        int n = i >> 4, d4 = i & 15;
        ((float4*)kc[n])[d4] = ((const float4*)(g_kcmp + ((size_t)n * Gn + g) * Dn))[d4];
        ((float4*)vc[n])[d4] = ((const float4*)(g_vcmp + ((size_t)n * Gn + g) * Dn))[d4];
    }
    for (int i = tid; i < HGn * 16; i += 128) {
        int hg = i >> 4, d4 = i & 15;
        ((float4*)qs[hg])[d4] = ((const float4*)(g_q + ((size_t)t * Hn + g * HGn + hg) * Dn))[d4];
    }
    __syncthreads();

    // head index for slot j: hh = w*HPW + j
    // ---- compressed branch ----
    const int nvis = (t + 1) >> 5;
    float sc[HPW][2];
    #pragma unroll
    for (int ii = 0; ii < 2; ii++) {
        const int n = lane + ii * 32;
        float a[HPW] = {0.f, 0.f, 0.f, 0.f};
        if (n < nvis) {
            const float4* k4 = (const float4*)kc[n];
            #pragma unroll
            for (int i = 0; i < 16; i++) {
                float4 kv = k4[i];
                #pragma unroll
                for (int j = 0; j < HPW; j++) {
                    float4 qv = ((const float4*)qs[w * HPW + j])[i];
                    a[j] = fmaf(qv.x, kv.x, a[j]);
                    a[j] = fmaf(qv.y, kv.y, a[j]);
                    a[j] = fmaf(qv.z, kv.z, a[j]);
                    a[j] = fmaf(qv.w, kv.w, a[j]);
                }
            }
        }
        #pragma unroll
        for (int j = 0; j < HPW; j++)
            sc[j][ii] = (n < nvis) ? a[j] * SCALEf : NEGf;
    }
    float c0[HPW], c1[HPW];
    #pragma unroll
    for (int j = 0; j < HPW; j++) {
        float p0 = 0.f, p1 = 0.f;
        if (nvis > 0) {
            float m = warpMax(fmaxf(sc[j][0], sc[j][1]));
            float e0 = expf(sc[j][0] - m), e1 = expf(sc[j][1] - m);
            float inv = 1.f / warpSum(e0 + e1);
            p0 = e0 * inv; p1 = e1 * inv;
        }
        ps[w * HPW + j][lane] = p0;
        ps[w * HPW + j][lane + 32] = p1;
        c0[j] = 0.f; c1[j] = 0.f;
    }
    __syncthreads();

    for (int n = 0; n < nvis; n++) {
        float2 v = *(const float2*)&vc[n][2 * lane];
        #pragma unroll
        for (int j = 0; j < HPW; j++) {
            const float p = ps[w * HPW + j][n];
            c0[j] = fmaf(p, v.x, c0[j]);
            c1[j] = fmaf(p, v.y, c1[j]);
        }
    }

    // ---- fused top-8 (warp 0; exact lowest-index-on-ties semantics) ----
    if (w == 0) {
        const int tb = t >> 5;
        float v0 = 0.f, v1 = 0.f;
        #pragma unroll
        for (int hg = 0; hg < HGn; hg++) { v0 += ps[hg][lane]; v1 += ps[hg][lane + 32]; }
        if (lane == 0)  v0 += 1e4f;
        if (lane == tb) v0 += 1e4f;
        if (lane + 32 == tb) v1 += 1e4f;
        if (lane > tb)      v0 = NEGf;
        if (lane + 32 > tb) v1 = NEGf;
        #pragma unroll
        for (int i = 0; i < NSELn; i++) {
            float bv = v0; int bi = lane;
            if (v1 > bv) { bv = v1; bi = lane + 32; }
            #pragma unroll
            for (int o = 16; o > 0; o >>= 1) {
                float ov = __shfl_xor_sync(0xffffffffu, bv, o);
                int   oi = __shfl_xor_sync(0xffffffffu, bi, o);
                if (ov > bv || (ov == bv && oi < bi)) { bv = ov; bi = oi; }
            }
            if (lane == 0) sel[i] = bi;
            if (bi == lane)      v0 = -2e30f;
            if (bi == lane + 32) v1 = -2e30f;
        }
    }
    __syncthreads();   // sel visible; cmp reads done -> safe to overwrite kc/vc rows 0-31

    // ---- selection branch (single pass, online softmax) ----
    float m[HPW], l[HPW], s0[HPW], s1[HPW];
    #pragma unroll
    for (int j = 0; j < HPW; j++) { m[j] = NEGf; l[j] = 0.f; s0[j] = 0.f; s1[j] = 0.f; }
    for (int i = 0; i < NSELn; i++) {
        const int base = sel[i] * BLKn;
        for (int ii = tid; ii < BLKn * 16; ii += 128) {
            int b = ii >> 4, d4 = ii & 15;
            ((float4*)kc[b])[d4] = ((const float4*)(g_k + ((size_t)(base + b) * HKVn + g) * Dn))[d4];
            ((float4*)vc[b])[d4] = ((const float4*)(g_qkvw + (size_t)(base + b) * OUTDn + VOFF + g * Dn))[d4];
        }
        __syncthreads();
        const int pos = base + lane;
        float a[HPW] = {0.f, 0.f, 0.f, 0.f};
        if (pos <= t) {
            const float4* k4 = (const float4*)kc[lane];
            #pragma unroll
            for (int ii = 0; ii < 16; ii++) {
                float4 kv = k4[ii];
                #pragma unroll
                for (int j = 0; j < HPW; j++) {
                    float4 qv = ((const float4*)qs[w * HPW + j])[ii];
                    a[j] = fmaf(qv.x, kv.x, a[j]);
                    a[j] = fmaf(qv.y, kv.y, a[j]);
                    a[j] = fmaf(qv.z, kv.z, a[j]);
                    a[j] = fmaf(qv.w, kv.w, a[j]);
                }
            }
        }
        #pragma unroll
        for (int j = 0; j < HPW; j++) {
            float s = (pos <= t) ? a[j] * SCALEf : NEGf;
            float mnew = fmaxf(m[j], warpMax(s));
            float corr = expf(m[j] - mnew);
            float e = (pos <= t) ? expf(s - mnew) : 0.f;
            ps[w * HPW + j][lane] = e;
            l[j] = l[j] * corr + warpSum(e);
            s0[j] *= corr; s1[j] *= corr;
            m[j] = mnew;
        }
        __syncwarp();
        for (int b = 0; b < BLKn; b++) {
            float2 v = *(const float2*)&vc[b][2 * lane];
            #pragma unroll
            for (int j = 0; j < HPW; j++) {
                const float p = ps[w * HPW + j][b];
                s0[j] = fmaf(p, v.x, s0[j]);
                s1[j] = fmaf(p, v.y, s1[j]);
            }
        }
        __syncthreads();
    }
    #pragma unroll
    for (int j = 0; j < HPW; j++) {
        float inv = 1.f / l[j];
        s0[j] *= inv; s1[j] *= inv;
    }

    // ---- sliding-window branch (single pass, online softmax) ----
    const int p0i = t - (WINn - 1);
    float wm_[HPW], wl[HPW], w0[HPW], w1[HPW];
    #pragma unroll
    for (int j = 0; j < HPW; j++) { wm_[j] = NEGf; wl[j] = 0.f; w0[j] = 0.f; w1[j] = 0.f; }
    for (int i = 0; i < 8; i++) {
        const int base = p0i + i * 32;
        for (int ii = tid; ii < BLKn * 16; ii += 128) {
            int b = ii >> 4, d4 = ii & 15;
            int row = base + b; if (row < 0) row = 0;
            ((float4*)kc[b])[d4] = ((const float4*)(g_k + ((size_t)row * HKVn + g) * Dn))[d4];
            ((float4*)vc[b])[d4] = ((const float4*)(g_qkvw + (size_t)row * OUTDn + VOFF + g * Dn))[d4];
        }
        __syncthreads();
        const int pos = base + lane;
        float a[HPW] = {0.f, 0.f, 0.f, 0.f};
        if (pos >= 0) {
            const float4* k4 = (const float4*)kc[lane];
            #pragma unroll
            for (int ii = 0; ii < 16; ii++) {
                float4 kv = k4[ii];
                #pragma unroll
                for (int j = 0; j < HPW; j++) {
                    float4 qv = ((const float4*)qs[w * HPW + j])[ii];
                    a[j] = fmaf(qv.x, kv.x, a[j]);
                    a[j] = fmaf(qv.y, kv.y, a[j]);
                    a[j] = fmaf(qv.z, kv.z, a[j]);
                    a[j] = fmaf(qv.w, kv.w, a[j]);
                }
            }
        }
        #pragma unroll
        for (int j = 0; j < HPW; j++) {
            float s = (pos >= 0) ? a[j] * SCALEf : NEGf;
            float mnew = fmaxf(wm_[j], warpMax(s));
            float corr = expf(wm_[j] - mnew);
            float e = (pos >= 0) ? expf(s - mnew) : 0.f;
            ps[w * HPW + j][lane] = e;
            wl[j] = wl[j] * corr + warpSum(e);
            w0[j] *= corr; w1[j] *= corr;
            wm_[j] = mnew;
        }
        __syncwarp();
        for (int b = 0; b < BLKn; b++) {
            float2 v = *(const float2*)&vc[b][2 * lane];
            #pragma unroll
            for (int j = 0; j < HPW; j++) {
                const float p = ps[w * HPW + j][b];
                w0[j] = fmaf(p, v.x, w0[j]);
                w1[j] = fmaf(p, v.y, w1[j]);
            }
        }
        __syncthreads();
    }

    // ---- gated combine -> packed 3-term bf16 operand ----
    #pragma unroll
    for (int j = 0; j < HPW; j++) {
        float inv = 1.f / wl[j];
        float ww0 = w0[j] * inv, ww1 = w1[j] * inv;
        const int h = g * HGn + w * HPW + j;
        const float* wrow = g_qkvw + (size_t)t * OUTDn + WOFF + h * 3;
        const float ga = 1.f / (1.f + expf(-wrow[0]));
        const float gb = 1.f / (1.f + expf(-wrow[1]));
        const float gc = 1.f / (1.f + expf(-wrow[2]));
        float o0 = ga * c0[j] + gb * s0[j] + gc * ww0;
        float o1 = ga * c1[j] + gb * s1[j] + gc * ww1;
        unsigned short h0, l0, h1, l1;
        f32_hl(o0, h0, l0);
        f32_hl(o1, h1, l1);
        const size_t idx = ((size_t)t * Hn + h) * Dn + 2 * lane;
        uint32_t* p = (uint32_t*)((unsigned short*)g_a2o + idx * 3);
        p[0] = (uint32_t)h0 | ((uint32_t)h0 << 16);
        p[1] = (uint32_t)l0 | ((uint32_t)h1 << 16);
        p[2] = (uint32_t)h1 | ((uint32_t)l1 << 16);
    }
}

// ---------------- launch ----------------
extern "C" void kernel_launch(void* const* d_in, const int* in_sizes, int n_in,
                              void* d_out, int out_size) {
    const float* x    = (const float*)d_in[0];
    const float* cosp = (const float*)d_in[1];
    const float* sinp = (const float*)d_in[2];
    const float* Wqkv = (const float*)d_in[3];
    const float* Wo   = (const float*)d_in[4];
    float* out = (float*)d_out;

    cudaFuncSetAttribute(gemm_mma_qkvw, cudaFuncAttributeMaxDynamicSharedMemorySize, GEMM_SMEM);
    cudaFuncSetAttribute(gemm_mma_out,  cudaFuncAttributeMaxDynamicSharedMemorySize, GEMM_SMEM);

    conv_x_kernel<<<(Tn * HIDn + 255) / 256, 256>>>(x);
    {
        dim3 b(32, 32);
        tr_q_kernel<<<dim3(76, 64), b>>>(Wqkv);
        tr_o_kernel<<<dim3(64, 64), b>>>(Wo);
    }
    gemm_mma_qkvw<<<dim3(NPADn / 128, Tn / 128), 512, GEMM_SMEM>>>();
    rope_kernel<<<(Tn * (Hn + HKVn) * Dn + 255) / 256, 256>>>(cosp, sinp);
    pool_kernel<<<(NBn * Gn * Dn + 255) / 256, 256>>>();
    att_kernel<<<dim3(Tn, Gn), 128>>>();
    gemm_mma_out<<<dim3(HIDn / 128, Tn / 128), 512, GEMM_SMEM>>>(out);
}